// round 1
// baseline (speedup 1.0000x reference)
#include <cuda_runtime.h>
#include <cstdint>
#include <cstddef>

// ---------------------------------------------------------------------------
// Problem constants (fixed shapes per reference setup_inputs)
// ---------------------------------------------------------------------------
#define NA   50000     // authors
#define NP   100000    // papers
#define NE   800000    // edges per edge list (writes, cites)
#define NEL  100000    // label edges
#define CDIM 256
#define FDIM 128

// ---------------------------------------------------------------------------
// Device global scratch (no allocations allowed in kernel_launch)
// ---------------------------------------------------------------------------
__device__ float g_xa0[(size_t)NA * CDIM];
__device__ float g_xa1[(size_t)NA * CDIM];
__device__ float g_xp0[(size_t)NP * CDIM];
__device__ float g_xp1[(size_t)NP * CDIM];
__device__ float g_aggW[(size_t)NP * CDIM];   // mean over writes  (author->paper)
__device__ float g_aggC[(size_t)NP * CDIM];   // mean over cites   (paper->paper)
__device__ float g_aggA[(size_t)NA * CDIM];   // mean over rev-writes (paper->author)
__device__ int   g_rpW[NP + 1];
__device__ int   g_rpC[NP + 1];
__device__ int   g_rpA[NA + 1];
__device__ int   g_colW[NE];
__device__ int   g_colC[NE];
__device__ int   g_colA[NE];
__device__ int   g_cntW[NP];
__device__ int   g_cntC[NP];
__device__ int   g_cntA[NA];
__device__ float g_Wcomb[CDIM * CDIM];        // Wr[t0] + Wr[t2] (or 128x256 layer1)
__device__ float g_bcomb[CDIM];
__device__ float g_Bcat[CDIM * 512];          // decoder [256 x 512] = [W1_top | W1_bot]
__device__ float g_TB[(size_t)NA * 512];      // xa_final @ Bcat

// ---------------------------------------------------------------------------
// CSR build: histogram -> exclusive scan -> fill
// ---------------------------------------------------------------------------
__global__ void k_hist(const int* __restrict__ wdst, const int* __restrict__ cdst,
                       const int* __restrict__ wsrc) {
    for (int e = blockIdx.x * blockDim.x + threadIdx.x; e < NE;
         e += gridDim.x * blockDim.x) {
        atomicAdd(&g_cntW[wdst[e]], 1);
        atomicAdd(&g_cntC[cdst[e]], 1);
        atomicAdd(&g_cntA[wsrc[e]], 1);
    }
}

// Single-block exclusive scan (n up to 100001). Warp-shuffle based.
__global__ void k_scan(const int* __restrict__ cnt, int* __restrict__ rp, int n) {
    __shared__ int wsum[32];
    __shared__ int carry;
    int t = threadIdx.x, lane = t & 31, wid = t >> 5;
    if (t == 0) carry = 0;
    __syncthreads();
    for (int base = 0; base < n; base += 1024) {
        int idx = base + t;
        int v = (idx < n) ? cnt[idx] : 0;
        int x = v;
        #pragma unroll
        for (int off = 1; off < 32; off <<= 1) {
            int y = __shfl_up_sync(0xffffffffu, x, off);
            if (lane >= off) x += y;
        }
        if (lane == 31) wsum[wid] = x;
        __syncthreads();
        if (wid == 0) {
            int s = wsum[lane];
            #pragma unroll
            for (int off = 1; off < 32; off <<= 1) {
                int y = __shfl_up_sync(0xffffffffu, s, off);
                if (lane >= off) s += y;
            }
            wsum[lane] = s;
        }
        __syncthreads();
        int offset = ((wid > 0) ? wsum[wid - 1] : 0) + carry;
        if (idx < n) rp[idx] = offset + x - v;   // exclusive
        __syncthreads();
        if (t == 0) carry += wsum[31];
        __syncthreads();
    }
    if (threadIdx.x == 0) rp[n] = carry;
}

__global__ void k_fill(const int* __restrict__ key, const int* __restrict__ val,
                       const int* __restrict__ rp, int* __restrict__ cur,
                       int* __restrict__ col) {
    for (int e = blockIdx.x * blockDim.x + threadIdx.x; e < NE;
         e += gridDim.x * blockDim.x) {
        int k = key[e];
        int pos = rp[k] + atomicAdd(&cur[k], 1);
        col[pos] = val[e];
    }
}

// ---------------------------------------------------------------------------
// Mean aggregation: one warp per destination row (CSR gather)
// ---------------------------------------------------------------------------
template <int DIM>
__global__ void k_agg(const float* __restrict__ xs, const int* __restrict__ rp,
                      const int* __restrict__ col, float* __restrict__ out, int ndst) {
    constexpr int NV = DIM / 128;  // float4 per lane
    int lane = threadIdx.x & 31;
    int w  = (blockIdx.x * blockDim.x + threadIdx.x) >> 5;
    int nw = (gridDim.x * blockDim.x) >> 5;
    for (int d = w; d < ndst; d += nw) {
        int e0 = rp[d], e1 = rp[d + 1];
        float4 acc[NV];
        #pragma unroll
        for (int v = 0; v < NV; v++) acc[v] = make_float4(0.f, 0.f, 0.f, 0.f);
        for (int e = e0; e < e1; e++) {
            const float4* row = (const float4*)(xs + (size_t)col[e] * DIM);
            #pragma unroll
            for (int v = 0; v < NV; v++) {
                float4 r = row[lane + 32 * v];
                acc[v].x += r.x; acc[v].y += r.y; acc[v].z += r.z; acc[v].w += r.w;
            }
        }
        float inv = 1.0f / (float)max(e1 - e0, 1);
        float4* orow = (float4*)(out + (size_t)d * DIM);
        #pragma unroll
        for (int v = 0; v < NV; v++) {
            acc[v].x *= inv; acc[v].y *= inv; acc[v].z *= inv; acc[v].w *= inv;
            orow[lane + 32 * v] = acc[v];
        }
    }
}

// ---------------------------------------------------------------------------
// Weight/bias combine: Wo = Wa + Wb (n elems), bo = ba + bb (256)
// ---------------------------------------------------------------------------
__global__ void k_combine(const float* __restrict__ Wa, const float* __restrict__ Wb,
                          const float* __restrict__ ba, const float* __restrict__ bb,
                          float* __restrict__ Wo, float* __restrict__ bo, int n) {
    for (int i = blockIdx.x * blockDim.x + threadIdx.x; i < n;
         i += gridDim.x * blockDim.x) {
        Wo[i] = Wa[i] + Wb[i];
        if (i < CDIM) bo[i] = ba[i] + bb[i];
    }
}

// Decoder Bcat: [256 x 512], cols 0..255 = W1 rows 0..255, cols 256..511 = rows 256..511
__global__ void k_bcat(const float* __restrict__ W1, float* __restrict__ Bcat) {
    for (int i = blockIdx.x * blockDim.x + threadIdx.x; i < CDIM * 512;
         i += gridDim.x * blockDim.x) {
        int k = i >> 9, j = i & 511;
        Bcat[i] = (j < 256) ? W1[k * 256 + j] : W1[(256 + k) * 256 + (j - 256)];
    }
}

// ---------------------------------------------------------------------------
// Multi-segment SGEMM: C = relu?( sum_s A_s @ B_s + bias )
// A_s row-major [M x K_s], B_s row-major [K_s x N], N % 128 == 0, K_s % 8 == 0.
// Block tile 128x128, thread tile 8x8, 256 threads.
// ---------------------------------------------------------------------------
#define BM 128
#define BN 128
#define BKk 8

__global__ void __launch_bounds__(256, 2)
k_gemm(int M, int N,
       const float* A0, const float* B0, int K0,
       const float* A1, const float* B1, int K1,
       const float* A2, const float* B2, int K2,
       const float* bias, float* Cmat, int relu) {
    __shared__ float As[BKk][BM];
    __shared__ float Bs[BKk][BN];
    int tid = threadIdx.x;
    int tx = tid & 15, ty = tid >> 4;
    int bm = blockIdx.y * BM;
    int bn = blockIdx.x * BN;

    float acc[8][8];
    #pragma unroll
    for (int i = 0; i < 8; i++)
        #pragma unroll
        for (int j = 0; j < 8; j++) acc[i][j] = 0.f;

    int ar = tid >> 1;            // 0..127
    int ac = (tid & 1) * 4;       // 0 or 4
    int br = tid >> 5;            // 0..7
    int bc = (tid & 31) * 4;      // 0..124

    #pragma unroll
    for (int s = 0; s < 3; s++) {
        const float* A = (s == 0) ? A0 : (s == 1) ? A1 : A2;
        const float* B = (s == 0) ? B0 : (s == 1) ? B1 : B2;
        int K = (s == 0) ? K0 : (s == 1) ? K1 : K2;
        if (A == nullptr) continue;
        for (int k0 = 0; k0 < K; k0 += BKk) {
            float4 av = make_float4(0.f, 0.f, 0.f, 0.f);
            int grow = bm + ar;
            if (grow < M) av = *(const float4*)(A + (size_t)grow * K + k0 + ac);
            As[ac + 0][ar] = av.x;
            As[ac + 1][ar] = av.y;
            As[ac + 2][ar] = av.z;
            As[ac + 3][ar] = av.w;
            float4 bv = *(const float4*)(B + (size_t)(k0 + br) * N + bn + bc);
            *(float4*)&Bs[br][bc] = bv;
            __syncthreads();
            #pragma unroll
            for (int kk = 0; kk < BKk; kk++) {
                float a[8], b[8];
                #pragma unroll
                for (int i = 0; i < 8; i++) a[i] = As[kk][ty * 8 + i];
                #pragma unroll
                for (int j = 0; j < 8; j++) b[j] = Bs[kk][tx * 8 + j];
                #pragma unroll
                for (int i = 0; i < 8; i++)
                    #pragma unroll
                    for (int j = 0; j < 8; j++) acc[i][j] += a[i] * b[j];
            }
            __syncthreads();
        }
    }

    #pragma unroll
    for (int i = 0; i < 8; i++) {
        int row = bm + ty * 8 + i;
        if (row >= M) break;
        #pragma unroll
        for (int j = 0; j < 8; j += 4) {
            int colb = bn + tx * 8 + j;
            float4 v;
            v.x = acc[i][j + 0] + (bias ? bias[colb + 0] : 0.f);
            v.y = acc[i][j + 1] + (bias ? bias[colb + 1] : 0.f);
            v.z = acc[i][j + 2] + (bias ? bias[colb + 2] : 0.f);
            v.w = acc[i][j + 3] + (bias ? bias[colb + 3] : 0.f);
            if (relu) {
                v.x = fmaxf(v.x, 0.f); v.y = fmaxf(v.y, 0.f);
                v.z = fmaxf(v.z, 0.f); v.w = fmaxf(v.w, 0.f);
            }
            *(float4*)(Cmat + (size_t)row * N + colb) = v;
        }
    }
}

// ---------------------------------------------------------------------------
// Fused edge decoder: out[e] = relu(TB[s][0:256] + TB[d][256:512] + b1) . W2 + b2
// One warp per edge.
// ---------------------------------------------------------------------------
__global__ void k_edge(const int* __restrict__ src, const int* __restrict__ dst,
                       const float* __restrict__ TB, const float* __restrict__ b1,
                       const float* __restrict__ W2, const float* __restrict__ b2,
                       float* __restrict__ out) {
    int lane = threadIdx.x & 31;
    int w  = (blockIdx.x * blockDim.x + threadIdx.x) >> 5;
    int nw = (gridDim.x * blockDim.x) >> 5;
    for (int e = w; e < NEL; e += nw) {
        int s = src[e], d = dst[e];
        const float* Ts = TB + (size_t)s * 512;
        const float* Td = TB + (size_t)d * 512 + 256;
        float sum = 0.f;
        #pragma unroll
        for (int k = 0; k < 8; k++) {
            int c = lane + 32 * k;
            float h = Ts[c] + Td[c] + b1[c];
            h = fmaxf(h, 0.f);
            sum += h * W2[c];
        }
        #pragma unroll
        for (int off = 16; off; off >>= 1)
            sum += __shfl_down_sync(0xffffffffu, sum, off);
        if (lane == 0) out[e] = sum + b2[0];
    }
}

// ---------------------------------------------------------------------------
// Host launch
// ---------------------------------------------------------------------------
template <typename T>
static T* sym_addr(const void* sym) {
    void* p = nullptr;
    cudaGetSymbolAddress(&p, sym);
    return (T*)p;
}

extern "C" void kernel_launch(void* const* d_in, const int* in_sizes, int n_in,
                              void* d_out, int out_size) {
    const float* x_author = (const float*)d_in[0];
    const float* x_paper  = (const float*)d_in[1];
    const float* Wl1      = (const float*)d_in[2];   // [3,128,256]
    const float* bl1      = (const float*)d_in[3];   // [3,256]
    const float* Wr1      = (const float*)d_in[4];   // [3,128,256]
    const float* Wl       = (const float*)d_in[5];   // [3,3,256,256]
    const float* bl       = (const float*)d_in[6];   // [3,3,256]
    const float* Wr       = (const float*)d_in[7];   // [3,3,256,256]
    const float* dec_W1   = (const float*)d_in[8];   // [512,256]
    const float* dec_b1   = (const float*)d_in[9];   // [256]
    const float* dec_W2   = (const float*)d_in[10];  // [256,1]
    const float* dec_b2   = (const float*)d_in[11];  // [1]
    const int* wsrc = (const int*)d_in[12];
    const int* wdst = (const int*)d_in[13];
    const int* csrc = (const int*)d_in[14];
    const int* cdst = (const int*)d_in[15];
    const int* esrc = (const int*)d_in[16];
    const int* edst = (const int*)d_in[17];
    float* out = (float*)d_out;

    float* xa[2] = {sym_addr<float>(g_xa0), sym_addr<float>(g_xa1)};
    float* xp[2] = {sym_addr<float>(g_xp0), sym_addr<float>(g_xp1)};
    float* aggW = sym_addr<float>(g_aggW);
    float* aggC = sym_addr<float>(g_aggC);
    float* aggA = sym_addr<float>(g_aggA);
    int* rpW = sym_addr<int>(g_rpW);
    int* rpC = sym_addr<int>(g_rpC);
    int* rpA = sym_addr<int>(g_rpA);
    int* colW = sym_addr<int>(g_colW);
    int* colC = sym_addr<int>(g_colC);
    int* colA = sym_addr<int>(g_colA);
    int* cntW = sym_addr<int>(g_cntW);
    int* cntC = sym_addr<int>(g_cntC);
    int* cntA = sym_addr<int>(g_cntA);
    float* Wcomb = sym_addr<float>(g_Wcomb);
    float* bcomb = sym_addr<float>(g_bcomb);
    float* Bcat  = sym_addr<float>(g_Bcat);
    float* TB    = sym_addr<float>(g_TB);

    const int TPB = 256;
    dim3 gP(2, (NP + BM - 1) / BM);   // paper GEMM grid (N=256)
    dim3 gA(2, (NA + BM - 1) / BM);   // author GEMM grid (N=256)
    dim3 gD(4, (NA + BM - 1) / BM);   // decoder GEMM grid (N=512)
    int aggBlkP = (NP * 32 + TPB - 1) / TPB;
    int aggBlkA = (NA * 32 + TPB - 1) / TPB;

    // ---- CSR build ----
    cudaMemsetAsync(cntW, 0, NP * sizeof(int));
    cudaMemsetAsync(cntC, 0, NP * sizeof(int));
    cudaMemsetAsync(cntA, 0, NA * sizeof(int));
    k_hist<<<1024, TPB>>>(wdst, cdst, wsrc);
    k_scan<<<1, 1024>>>(cntW, rpW, NP);
    k_scan<<<1, 1024>>>(cntC, rpC, NP);
    k_scan<<<1, 1024>>>(cntA, rpA, NA);
    cudaMemsetAsync(cntW, 0, NP * sizeof(int));
    cudaMemsetAsync(cntC, 0, NP * sizeof(int));
    cudaMemsetAsync(cntA, 0, NA * sizeof(int));
    k_fill<<<1024, TPB>>>(wdst, wsrc, rpW, cntW, colW);
    k_fill<<<1024, TPB>>>(cdst, csrc, rpC, cntC, colC);
    k_fill<<<1024, TPB>>>(wsrc, wdst, rpA, cntA, colA);

    // ---- Layer 1 (F=128 inputs) ----
    k_agg<128><<<aggBlkP, TPB>>>(x_author, rpW, colW, aggW, NP);
    k_agg<128><<<aggBlkP, TPB>>>(x_paper,  rpC, colC, aggC, NP);
    k_agg<128><<<aggBlkA, TPB>>>(x_paper,  rpA, colA, aggA, NA);
    k_combine<<<128, TPB>>>(Wr1 + 0 * FDIM * CDIM, Wr1 + 2 * FDIM * CDIM,
                            bl1 + 0 * CDIM, bl1 + 2 * CDIM, Wcomb, bcomb,
                            FDIM * CDIM);
    // paper: [aggW|aggC|xp] @ [Wl1_0; Wl1_2; Wr1_0+Wr1_2] + (bl1_0+bl1_2), relu
    k_gemm<<<gP, TPB>>>(NP, CDIM,
                        aggW, Wl1 + 0 * FDIM * CDIM, FDIM,
                        aggC, Wl1 + 2 * FDIM * CDIM, FDIM,
                        x_paper, Wcomb, FDIM,
                        bcomb, xp[0], 1);
    // author: [aggA|xa] @ [Wl1_1; Wr1_1] + bl1_1, relu
    k_gemm<<<gA, TPB>>>(NA, CDIM,
                        aggA, Wl1 + 1 * FDIM * CDIM, FDIM,
                        x_author, Wr1 + 1 * FDIM * CDIM, FDIM,
                        nullptr, nullptr, 0,
                        bl1 + 1 * CDIM, xa[0], 1);

    // ---- Layers 2..4 (C=256) ----
    int cur = 0;
    for (int l = 0; l < 3; l++) {
        k_agg<256><<<aggBlkP, TPB>>>(xa[cur], rpW, colW, aggW, NP);
        k_agg<256><<<aggBlkP, TPB>>>(xp[cur], rpC, colC, aggC, NP);
        k_agg<256><<<aggBlkA, TPB>>>(xp[cur], rpA, colA, aggA, NA);
        const float* Wl_l = Wl + (size_t)l * 3 * CDIM * CDIM;
        const float* Wr_l = Wr + (size_t)l * 3 * CDIM * CDIM;
        const float* bl_l = bl + (size_t)l * 3 * CDIM;
        k_combine<<<256, TPB>>>(Wr_l + 0 * CDIM * CDIM, Wr_l + 2 * CDIM * CDIM,
                                bl_l + 0 * CDIM, bl_l + 2 * CDIM, Wcomb, bcomb,
                                CDIM * CDIM);
        int relu = (l < 2) ? 1 : 0;
        k_gemm<<<gP, TPB>>>(NP, CDIM,
                            aggW, Wl_l + 0 * CDIM * CDIM, CDIM,
                            aggC, Wl_l + 2 * CDIM * CDIM, CDIM,
                            xp[cur], Wcomb, CDIM,
                            bcomb, xp[1 - cur], relu);
        k_gemm<<<gA, TPB>>>(NA, CDIM,
                            aggA, Wl_l + 1 * CDIM * CDIM, CDIM,
                            xa[cur], Wr_l + 1 * CDIM * CDIM, CDIM,
                            nullptr, nullptr, 0,
                            bl_l + 1 * CDIM, xa[1 - cur], relu);
        cur ^= 1;
    }

    // ---- Decoder ----
    k_bcat<<<256, TPB>>>(dec_W1, Bcat);
    k_gemm<<<gD, TPB>>>(NA, 512,
                        xa[cur], Bcat, CDIM,
                        nullptr, nullptr, 0,
                        nullptr, nullptr, 0,
                        nullptr, TB, 0);
    k_edge<<<(NEL * 32 + TPB - 1) / TPB, TPB>>>(esrc, edst, TB, dec_b1, dec_W2,
                                                dec_b2, out);
}

// round 3
// speedup vs baseline: 1.7862x; 1.7862x over previous
#include <cuda_runtime.h>
#include <cuda_bf16.h>
#include <cstdint>
#include <cstddef>

// ---------------------------------------------------------------------------
// Problem constants
// ---------------------------------------------------------------------------
#define NA   50000
#define NP   100000
#define NE   800000
#define NEL  100000
#define CD   256

// ---------------------------------------------------------------------------
// Device scratch: activations as separate hi/lo bf16 planes
// ---------------------------------------------------------------------------
__device__ __nv_bfloat16 g_xaH[2][(size_t)NA * CD];
__device__ __nv_bfloat16 g_xaL[2][(size_t)NA * CD];
__device__ __nv_bfloat16 g_xpH[2][(size_t)NP * CD];
__device__ __nv_bfloat16 g_xpL[2][(size_t)NP * CD];
__device__ __nv_bfloat16 g_aWH[(size_t)NP * CD];
__device__ __nv_bfloat16 g_aWL[(size_t)NP * CD];
__device__ __nv_bfloat16 g_aCH[(size_t)NP * CD];
__device__ __nv_bfloat16 g_aCL[(size_t)NP * CD];
__device__ __nv_bfloat16 g_aAH[(size_t)NA * CD];
__device__ __nv_bfloat16 g_aAL[(size_t)NA * CD];
__device__ __nv_bfloat16 g_xinAH[(size_t)NA * 128];
__device__ __nv_bfloat16 g_xinAL[(size_t)NA * 128];
__device__ __nv_bfloat16 g_xinPH[(size_t)NP * 128];
__device__ __nv_bfloat16 g_xinPL[(size_t)NP * 128];
__device__ __nv_bfloat16 g_BPh[256 * 768];
__device__ __nv_bfloat16 g_BPl[256 * 768];
__device__ __nv_bfloat16 g_BAh[256 * 512];
__device__ __nv_bfloat16 g_BAl[256 * 512];
__device__ __nv_bfloat16 g_BDh[512 * 256];
__device__ __nv_bfloat16 g_BDl[512 * 256];
__device__ float g_bcomb[256];
__device__ float g_TB[(size_t)NA * 512];
// CSR
__device__ int g_rpW[NP + 1];
__device__ int g_rpC[NP + 1];
__device__ int g_rpA[NA + 1];
__device__ int g_colW[NE];
__device__ int g_colC[NE];
__device__ int g_colA[NE];
__device__ int g_cntW[NP];
__device__ int g_cntC[NP];
__device__ int g_cntA[NA];

// ---------------------------------------------------------------------------
// Baseline-PTX helpers (sm_80+: mma.sync bf16, ldmatrix, cp.async)
// ---------------------------------------------------------------------------
__device__ __forceinline__ uint32_t smem_u32(const void* p) {
    uint32_t a;
    asm("{ .reg .u64 t; cvta.to.shared.u64 t, %1; cvt.u32.u64 %0, t; }"
        : "=r"(a) : "l"(p));
    return a;
}
__device__ __forceinline__ void cpasync16(uint32_t dst, const void* src, int sz) {
    asm volatile("cp.async.cg.shared.global [%0], [%1], 16, %2;"
                 :: "r"(dst), "l"(src), "r"(sz) : "memory");
}
#define CP_COMMIT() asm volatile("cp.async.commit_group;" ::: "memory")
#define CP_WAIT1()  asm volatile("cp.async.wait_group 1;" ::: "memory")
#define CP_WAIT0()  asm volatile("cp.async.wait_group 0;" ::: "memory")

__device__ __forceinline__ void ldsm4(uint32_t* r, uint32_t addr) {
    asm volatile("ldmatrix.sync.aligned.m8n8.x4.shared.b16 {%0,%1,%2,%3}, [%4];"
                 : "=r"(r[0]), "=r"(r[1]), "=r"(r[2]), "=r"(r[3]) : "r"(addr));
}
__device__ __forceinline__ void mma16816(float* c, const uint32_t* a, const uint32_t* b) {
    asm volatile(
        "mma.sync.aligned.m16n8k16.row.col.f32.bf16.bf16.f32 "
        "{%0,%1,%2,%3}, {%4,%5,%6,%7}, {%8,%9}, {%0,%1,%2,%3};"
        : "+f"(c[0]), "+f"(c[1]), "+f"(c[2]), "+f"(c[3])
        : "r"(a[0]), "r"(a[1]), "r"(a[2]), "r"(a[3]), "r"(b[0]), "r"(b[1]));
}

// ---------------------------------------------------------------------------
// Split-precision helpers
// ---------------------------------------------------------------------------
__device__ __forceinline__ float2 cvt2(uint32_t w) {
    __nv_bfloat162 b = *reinterpret_cast<__nv_bfloat162*>(&w);
    return __bfloat1622float2(b);
}
__device__ __forceinline__ void split1(float v, __nv_bfloat16& h, __nv_bfloat16& l) {
    h = __float2bfloat16(v);
    l = __float2bfloat16(v - __bfloat162float(h));
}
__device__ __forceinline__ uint32_t packbf2(__nv_bfloat16 a, __nv_bfloat16 b) {
    __nv_bfloat162 p = __halves2bfloat162(a, b);
    return *reinterpret_cast<uint32_t*>(&p);
}

// ---------------------------------------------------------------------------
// CSR build
// ---------------------------------------------------------------------------
__global__ void k_hist(const int* __restrict__ wdst, const int* __restrict__ cdst,
                       const int* __restrict__ wsrc) {
    for (int e = blockIdx.x * blockDim.x + threadIdx.x; e < NE; e += gridDim.x * blockDim.x) {
        atomicAdd(&g_cntW[wdst[e]], 1);
        atomicAdd(&g_cntC[cdst[e]], 1);
        atomicAdd(&g_cntA[wsrc[e]], 1);
    }
}

__global__ void k_scan(const int* __restrict__ cnt, int* __restrict__ rp, int n) {
    __shared__ int wsum[32];
    __shared__ int carry;
    int t = threadIdx.x, lane = t & 31, wid = t >> 5;
    if (t == 0) carry = 0;
    __syncthreads();
    for (int base = 0; base < n; base += 1024) {
        int idx = base + t;
        int v = (idx < n) ? cnt[idx] : 0;
        int x = v;
        #pragma unroll
        for (int off = 1; off < 32; off <<= 1) {
            int y = __shfl_up_sync(0xffffffffu, x, off);
            if (lane >= off) x += y;
        }
        if (lane == 31) wsum[wid] = x;
        __syncthreads();
        if (wid == 0) {
            int s = wsum[lane];
            #pragma unroll
            for (int off = 1; off < 32; off <<= 1) {
                int y = __shfl_up_sync(0xffffffffu, s, off);
                if (lane >= off) s += y;
            }
            wsum[lane] = s;
        }
        __syncthreads();
        int offset = ((wid > 0) ? wsum[wid - 1] : 0) + carry;
        if (idx < n) rp[idx] = offset + x - v;
        __syncthreads();
        if (t == 0) carry += wsum[31];
        __syncthreads();
    }
    if (threadIdx.x == 0) rp[n] = carry;
}

__global__ void k_fill(const int* __restrict__ key, const int* __restrict__ val,
                       const int* __restrict__ rp, int* __restrict__ cur,
                       int* __restrict__ col) {
    for (int e = blockIdx.x * blockDim.x + threadIdx.x; e < NE; e += gridDim.x * blockDim.x) {
        int k = key[e];
        int pos = rp[k] + atomicAdd(&cur[k], 1);
        col[pos] = val[e];
    }
}

// ---------------------------------------------------------------------------
// fp32 -> hi/lo planes
// ---------------------------------------------------------------------------
__global__ void k_split(const float* __restrict__ x, __nv_bfloat16* __restrict__ oh,
                        __nv_bfloat16* __restrict__ ol, int n) {
    for (int i = blockIdx.x * blockDim.x + threadIdx.x; i < n; i += gridDim.x * blockDim.x) {
        __nv_bfloat16 h, l;
        split1(x[i], h, l);
        oh[i] = h;
        ol[i] = l;
    }
}

// ---------------------------------------------------------------------------
// Mean aggregation over hi/lo planes (one warp per destination)
// ---------------------------------------------------------------------------
template <int DIM>
__global__ void k_aggp(const __nv_bfloat16* __restrict__ xh,
                       const __nv_bfloat16* __restrict__ xl,
                       const int* __restrict__ rp, const int* __restrict__ col,
                       __nv_bfloat16* __restrict__ oh, __nv_bfloat16* __restrict__ ol,
                       int ndst) {
    constexpr int EPL = DIM / 32;   // elems per lane (4 or 8)
    constexpr int W = EPL / 2;      // uint32 words per lane (2 or 4)
    int lane = threadIdx.x & 31;
    int w  = (blockIdx.x * blockDim.x + threadIdx.x) >> 5;
    int nw = (gridDim.x * blockDim.x) >> 5;
    for (int d = w; d < ndst; d += nw) {
        int e0 = rp[d], e1 = rp[d + 1];
        float acc[EPL];
        #pragma unroll
        for (int j = 0; j < EPL; j++) acc[j] = 0.f;
        for (int e = e0; e < e1; e++) {
            size_t base = (size_t)col[e] * DIM + lane * EPL;
            uint32_t wh[W], wl[W];
            if (W == 4) {
                *(uint4*)wh = *(const uint4*)(xh + base);
                *(uint4*)wl = *(const uint4*)(xl + base);
            } else {
                *(uint2*)wh = *(const uint2*)(xh + base);
                *(uint2*)wl = *(const uint2*)(xl + base);
            }
            #pragma unroll
            for (int j = 0; j < W; j++) {
                float2 fh = cvt2(wh[j]), fl = cvt2(wl[j]);
                acc[2 * j]     += fh.x + fl.x;
                acc[2 * j + 1] += fh.y + fl.y;
            }
        }
        float inv = 1.0f / (float)max(e1 - e0, 1);
        uint32_t ohw[W], olw[W];
        #pragma unroll
        for (int j = 0; j < W; j++) {
            __nv_bfloat16 h0, l0, h1, l1;
            split1(acc[2 * j] * inv, h0, l0);
            split1(acc[2 * j + 1] * inv, h1, l1);
            ohw[j] = packbf2(h0, h1);
            olw[j] = packbf2(l0, l1);
        }
        size_t obase = (size_t)d * DIM + lane * EPL;
        if (W == 4) {
            *(uint4*)(oh + obase) = *(uint4*)ohw;
            *(uint4*)(ol + obase) = *(uint4*)olw;
        } else {
            *(uint2*)(oh + obase) = *(uint2*)ohw;
            *(uint2*)(ol + obase) = *(uint2*)olw;
        }
    }
}

// ---------------------------------------------------------------------------
// Weight prep: B planes [256 x Ktot] from row-major W segments [Kseg,256]
// ---------------------------------------------------------------------------
__global__ void k_prepB(const float* __restrict__ W0, const float* __restrict__ W1s,
                        const float* __restrict__ W2a, const float* __restrict__ W2b,
                        int Kseg, int Ktot,
                        __nv_bfloat16* __restrict__ Bh, __nv_bfloat16* __restrict__ Bl) {
    int tot = 256 * Ktot;
    for (int i = blockIdx.x * blockDim.x + threadIdx.x; i < tot; i += gridDim.x * blockDim.x) {
        int n = i / Ktot, kg = i - n * Ktot;
        int seg = kg / Kseg, k = kg - seg * Kseg;
        float v;
        if (seg == 0)      v = W0[k * 256 + n];
        else if (seg == 1) v = W1s[k * 256 + n];
        else               v = W2a[k * 256 + n] + W2b[k * 256 + n];
        __nv_bfloat16 h, l;
        split1(v, h, l);
        Bh[i] = h;
        Bl[i] = l;
    }
}

__global__ void k_prepDec(const float* __restrict__ W1,
                          __nv_bfloat16* __restrict__ Bh, __nv_bfloat16* __restrict__ Bl) {
    for (int i = blockIdx.x * blockDim.x + threadIdx.x; i < 512 * 256;
         i += gridDim.x * blockDim.x) {
        int n = i >> 8, k = i & 255;
        float v = (n < 256) ? W1[k * 256 + n] : W1[(256 + k) * 256 + (n - 256)];
        __nv_bfloat16 h, l;
        split1(v, h, l);
        Bh[i] = h;
        Bl[i] = l;
    }
}

__global__ void k_biascomb(const float* __restrict__ a, const float* __restrict__ b,
                           float* __restrict__ o) {
    int i = threadIdx.x;
    if (i < 256) o[i] = a[i] + b[i];
}

// ---------------------------------------------------------------------------
// Split-bf16 tensor-core GEMM (mma.sync m16n8k16, cp.async double buffer)
// C[M, 128-slice of Nall] = sum_seg A_seg @ B^T, 3 products Ah*Bh+Ah*Bl+Al*Bh
// A planes: [M, Kseg] bf16 (up to 3 segments). B planes: [Nall, Ktot] bf16.
// Block: 128x128x32, 256 threads (8 warps, warp tile 64x32).
// ---------------------------------------------------------------------------
#define ROWB   80           // padded smem row stride in bytes (32 bf16 + 8 pad)
#define PLANE  10240        // 128 * 80
#define OFF_AH 0
#define OFF_AL 10240
#define OFF_BH 20480
#define OFF_BL 30720
#define STAGE  40960
#define SMEM_TOTAL (2 * STAGE)

__device__ __forceinline__ void stage_load(
    uint32_t sb, int stg, int tid, int bm, int n_off, int M, int Ktot, int Kseg, int s,
    const __nv_bfloat16* A0h, const __nv_bfloat16* A0l,
    const __nv_bfloat16* A1h, const __nv_bfloat16* A1l,
    const __nv_bfloat16* A2h, const __nv_bfloat16* A2l,
    const __nv_bfloat16* Bh, const __nv_bfloat16* Bl) {
    int kg = s * 32;
    int seg = kg / Kseg;
    int kof = kg - seg * Kseg;
    const __nv_bfloat16* ah = (seg == 0) ? A0h : (seg == 1) ? A1h : A2h;
    const __nv_bfloat16* al = (seg == 0) ? A0l : (seg == 1) ? A1l : A2l;
    uint32_t base = sb + stg * STAGE;
    #pragma unroll
    for (int i = 0; i < 2; i++) {
        int c = tid + 256 * i;
        int row = c >> 2, kc = c & 3;
        uint32_t d = base + row * ROWB + kc * 16;
        int gr = bm + row;
        int sz = (gr < M) ? 16 : 0;
        int grc = (gr < M) ? gr : (M - 1);
        size_t aoff = (size_t)grc * Kseg + kof + kc * 8;
        cpasync16(d + OFF_AH, ah + aoff, sz);
        cpasync16(d + OFF_AL, al + aoff, sz);
        size_t boff = (size_t)(n_off + row) * Ktot + kg + kc * 8;
        cpasync16(d + OFF_BH, Bh + boff, 16);
        cpasync16(d + OFF_BL, Bl + boff, 16);
    }
}

__global__ void __launch_bounds__(256, 2)
k_mgemm(int M, int Ktot, int Kseg, int Nall, int relu,
        const __nv_bfloat16* __restrict__ A0h, const __nv_bfloat16* __restrict__ A0l,
        const __nv_bfloat16* __restrict__ A1h, const __nv_bfloat16* __restrict__ A1l,
        const __nv_bfloat16* __restrict__ A2h, const __nv_bfloat16* __restrict__ A2l,
        const __nv_bfloat16* __restrict__ Bhg, const __nv_bfloat16* __restrict__ Blg,
        const float* __restrict__ bias,
        float* __restrict__ Cf,
        __nv_bfloat16* __restrict__ Ch, __nv_bfloat16* __restrict__ Cl) {
    extern __shared__ char smem[];
    uint32_t sb = smem_u32(smem);
    int tid = threadIdx.x;
    int lane = tid & 31;
    int warp = tid >> 5;
    int wm = warp >> 2;      // 0..1 (M)
    int wn = warp & 3;       // 0..3 (N)
    int bm = blockIdx.y * 128;
    int n_off = blockIdx.x * 128;
    int S = Ktot / 32;

    float acc[4][4][4];
    #pragma unroll
    for (int a = 0; a < 4; a++)
        #pragma unroll
        for (int b = 0; b < 4; b++)
            #pragma unroll
            for (int c = 0; c < 4; c++) acc[a][b][c] = 0.f;

    // per-lane ldmatrix address component: row (lane&15), k-group (lane>>4)
    uint32_t lmo = (uint32_t)((lane & 15) * ROWB + (lane >> 4) * 16);

    stage_load(sb, 0, tid, bm, n_off, M, Ktot, Kseg, 0,
               A0h, A0l, A1h, A1l, A2h, A2l, Bhg, Blg);
    CP_COMMIT();

    for (int s = 0; s < S; s++) {
        if (s + 1 < S) {
            stage_load(sb, (s + 1) & 1, tid, bm, n_off, M, Ktot, Kseg, s + 1,
                       A0h, A0l, A1h, A1l, A2h, A2l, Bhg, Blg);
            CP_COMMIT();
            CP_WAIT1();
        } else {
            CP_WAIT0();
        }
        __syncthreads();

        uint32_t base = sb + (s & 1) * STAGE;
        #pragma unroll
        for (int ks = 0; ks < 2; ks++) {
            uint32_t kb = ks * 32;  // 16 elems * 2B
            uint32_t af[4][4], bhf[4][2], blf[4][2];
            #pragma unroll
            for (int mt = 0; mt < 4; mt++)
                ldsm4(af[mt], base + OFF_AH + (wm * 64 + mt * 16) * ROWB + kb + lmo);
            #pragma unroll
            for (int bt = 0; bt < 2; bt++) {
                uint32_t r[4];
                ldsm4(r, base + OFF_BH + (wn * 32 + bt * 16) * ROWB + kb + lmo);
                bhf[2 * bt][0] = r[0]; bhf[2 * bt][1] = r[2];
                bhf[2 * bt + 1][0] = r[1]; bhf[2 * bt + 1][1] = r[3];
            }
            #pragma unroll
            for (int bt = 0; bt < 2; bt++) {
                uint32_t r[4];
                ldsm4(r, base + OFF_BL + (wn * 32 + bt * 16) * ROWB + kb + lmo);
                blf[2 * bt][0] = r[0]; blf[2 * bt][1] = r[2];
                blf[2 * bt + 1][0] = r[1]; blf[2 * bt + 1][1] = r[3];
            }
            #pragma unroll
            for (int mt = 0; mt < 4; mt++)
                #pragma unroll
                for (int nt = 0; nt < 4; nt++) mma16816(acc[mt][nt], af[mt], bhf[nt]);
            #pragma unroll
            for (int mt = 0; mt < 4; mt++)
                #pragma unroll
                for (int nt = 0; nt < 4; nt++) mma16816(acc[mt][nt], af[mt], blf[nt]);
            #pragma unroll
            for (int mt = 0; mt < 4; mt++)
                ldsm4(af[mt], base + OFF_AL + (wm * 64 + mt * 16) * ROWB + kb + lmo);
            #pragma unroll
            for (int mt = 0; mt < 4; mt++)
                #pragma unroll
                for (int nt = 0; nt < 4; nt++) mma16816(acc[mt][nt], af[mt], bhf[nt]);
        }
        __syncthreads();
    }

    // Epilogue
    #pragma unroll
    for (int mt = 0; mt < 4; mt++) {
        int r0 = bm + wm * 64 + mt * 16 + (lane >> 2);
        #pragma unroll
        for (int half = 0; half < 2; half++) {
            int row = r0 + half * 8;
            if (row >= M) continue;
            #pragma unroll
            for (int nt = 0; nt < 4; nt++) {
                int gcol = n_off + wn * 32 + nt * 8 + (lane & 3) * 2;
                float v0 = acc[mt][nt][half * 2 + 0];
                float v1 = acc[mt][nt][half * 2 + 1];
                if (Cf) {
                    float2 v = make_float2(v0, v1);
                    *(float2*)(Cf + (size_t)row * Nall + gcol) = v;
                } else {
                    v0 += bias[gcol];
                    v1 += bias[gcol + 1];
                    if (relu) { v0 = fmaxf(v0, 0.f); v1 = fmaxf(v1, 0.f); }
                    __nv_bfloat16 h0, l0, h1, l1;
                    split1(v0, h0, l0);
                    split1(v1, h1, l1);
                    *(uint32_t*)(Ch + (size_t)row * Nall + gcol) = packbf2(h0, h1);
                    *(uint32_t*)(Cl + (size_t)row * Nall + gcol) = packbf2(l0, l1);
                }
            }
        }
    }
}

// ---------------------------------------------------------------------------
// Fused edge decoder (reads fp32 TB)
// ---------------------------------------------------------------------------
__global__ void k_edge(const int* __restrict__ src, const int* __restrict__ dst,
                       const float* __restrict__ TB, const float* __restrict__ b1,
                       const float* __restrict__ W2, const float* __restrict__ b2,
                       float* __restrict__ out) {
    int lane = threadIdx.x & 31;
    int w  = (blockIdx.x * blockDim.x + threadIdx.x) >> 5;
    int nw = (gridDim.x * blockDim.x) >> 5;
    for (int e = w; e < NEL; e += nw) {
        int s = src[e], d = dst[e];
        const float* Ts = TB + (size_t)s * 512;
        const float* Td = TB + (size_t)d * 512 + 256;
        float sum = 0.f;
        #pragma unroll
        for (int k = 0; k < 8; k++) {
            int c = lane + 32 * k;
            float h = Ts[c] + Td[c] + b1[c];
            h = fmaxf(h, 0.f);
            sum += h * W2[c];
        }
        #pragma unroll
        for (int off = 16; off; off >>= 1)
            sum += __shfl_down_sync(0xffffffffu, sum, off);
        if (lane == 0) out[e] = sum + b2[0];
    }
}

// ---------------------------------------------------------------------------
// Host
// ---------------------------------------------------------------------------
template <typename T>
static T* sym_addr(const void* sym) {
    void* p = nullptr;
    cudaGetSymbolAddress(&p, sym);
    return (T*)p;
}

extern "C" void kernel_launch(void* const* d_in, const int* in_sizes, int n_in,
                              void* d_out, int out_size) {
    const float* x_author = (const float*)d_in[0];
    const float* x_paper  = (const float*)d_in[1];
    const float* Wl1      = (const float*)d_in[2];
    const float* bl1      = (const float*)d_in[3];
    const float* Wr1      = (const float*)d_in[4];
    const float* Wl       = (const float*)d_in[5];
    const float* bl       = (const float*)d_in[6];
    const float* Wr       = (const float*)d_in[7];
    const float* dec_W1   = (const float*)d_in[8];
    const float* dec_b1   = (const float*)d_in[9];
    const float* dec_W2   = (const float*)d_in[10];
    const float* dec_b2   = (const float*)d_in[11];
    const int* wsrc = (const int*)d_in[12];
    const int* wdst = (const int*)d_in[13];
    const int* csrc = (const int*)d_in[14];
    const int* cdst = (const int*)d_in[15];
    const int* esrc = (const int*)d_in[16];
    const int* edst = (const int*)d_in[17];
    float* out = (float*)d_out;

    typedef __nv_bfloat16 bf;
    bf* xaH[2] = {sym_addr<bf>(g_xaH), sym_addr<bf>(g_xaH) + (size_t)NA * CD};
    bf* xaL[2] = {sym_addr<bf>(g_xaL), sym_addr<bf>(g_xaL) + (size_t)NA * CD};
    bf* xpH[2] = {sym_addr<bf>(g_xpH), sym_addr<bf>(g_xpH) + (size_t)NP * CD};
    bf* xpL[2] = {sym_addr<bf>(g_xpL), sym_addr<bf>(g_xpL) + (size_t)NP * CD};
    bf* aWH = sym_addr<bf>(g_aWH); bf* aWL = sym_addr<bf>(g_aWL);
    bf* aCH = sym_addr<bf>(g_aCH); bf* aCL = sym_addr<bf>(g_aCL);
    bf* aAH = sym_addr<bf>(g_aAH); bf* aAL = sym_addr<bf>(g_aAL);
    bf* xinAH = sym_addr<bf>(g_xinAH); bf* xinAL = sym_addr<bf>(g_xinAL);
    bf* xinPH = sym_addr<bf>(g_xinPH); bf* xinPL = sym_addr<bf>(g_xinPL);
    bf* BPh = sym_addr<bf>(g_BPh); bf* BPl = sym_addr<bf>(g_BPl);
    bf* BAh = sym_addr<bf>(g_BAh); bf* BAl = sym_addr<bf>(g_BAl);
    bf* BDh = sym_addr<bf>(g_BDh); bf* BDl = sym_addr<bf>(g_BDl);
    float* bcomb = sym_addr<float>(g_bcomb);
    float* TB = sym_addr<float>(g_TB);
    int* rpW = sym_addr<int>(g_rpW);
    int* rpC = sym_addr<int>(g_rpC);
    int* rpA = sym_addr<int>(g_rpA);
    int* colW = sym_addr<int>(g_colW);
    int* colC = sym_addr<int>(g_colC);
    int* colA = sym_addr<int>(g_colA);
    int* cntW = sym_addr<int>(g_cntW);
    int* cntC = sym_addr<int>(g_cntC);
    int* cntA = sym_addr<int>(g_cntA);

    cudaFuncSetAttribute(k_mgemm, cudaFuncAttributeMaxDynamicSharedMemorySize, SMEM_TOTAL);

    const int TPB = 256;
    dim3 gP(2, (NP + 127) / 128);
    dim3 gA(2, (NA + 127) / 128);
    dim3 gD(4, (NA + 127) / 128);
    int aggBlkP = (NP * 32 + TPB - 1) / TPB;
    int aggBlkA = (NA * 32 + TPB - 1) / TPB;

    // ---- CSR build ----
    cudaMemsetAsync(cntW, 0, NP * sizeof(int));
    cudaMemsetAsync(cntC, 0, NP * sizeof(int));
    cudaMemsetAsync(cntA, 0, NA * sizeof(int));
    k_hist<<<1024, TPB>>>(wdst, cdst, wsrc);
    k_scan<<<1, 1024>>>(cntW, rpW, NP);
    k_scan<<<1, 1024>>>(cntC, rpC, NP);
    k_scan<<<1, 1024>>>(cntA, rpA, NA);
    cudaMemsetAsync(cntW, 0, NP * sizeof(int));
    cudaMemsetAsync(cntC, 0, NP * sizeof(int));
    cudaMemsetAsync(cntA, 0, NA * sizeof(int));
    k_fill<<<1024, TPB>>>(wdst, wsrc, rpW, cntW, colW);
    k_fill<<<1024, TPB>>>(cdst, csrc, rpC, cntC, colC);
    k_fill<<<1024, TPB>>>(wsrc, wdst, rpA, cntA, colA);

    // ---- Split fp32 inputs to hi/lo planes ----
    k_split<<<2048, TPB>>>(x_author, xinAH, xinAL, NA * 128);
    k_split<<<2048, TPB>>>(x_paper,  xinPH, xinPL, NP * 128);

    // ---- Layer 1 (Kseg = 128) ----
    k_aggp<128><<<aggBlkP, TPB>>>(xinAH, xinAL, rpW, colW, aWH, aWL, NP);
    k_aggp<128><<<aggBlkP, TPB>>>(xinPH, xinPL, rpC, colC, aCH, aCL, NP);
    k_aggp<128><<<aggBlkA, TPB>>>(xinPH, xinPL, rpA, colA, aAH, aAL, NA);
    k_prepB<<<384, TPB>>>(Wl1 + 0 * 128 * 256, Wl1 + 2 * 128 * 256,
                          Wr1 + 0 * 128 * 256, Wr1 + 2 * 128 * 256,
                          128, 384, BPh, BPl);
    k_biascomb<<<1, 256>>>(bl1 + 0 * 256, bl1 + 2 * 256, bcomb);
    k_prepB<<<256, TPB>>>(Wl1 + 1 * 128 * 256, Wr1 + 1 * 128 * 256,
                          nullptr, nullptr, 128, 256, BAh, BAl);
    k_mgemm<<<gP, TPB, SMEM_TOTAL>>>(NP, 384, 128, 256, 1,
                                     aWH, aWL, aCH, aCL, xinPH, xinPL,
                                     BPh, BPl, bcomb, nullptr, xpH[0], xpL[0]);
    k_mgemm<<<gA, TPB, SMEM_TOTAL>>>(NA, 256, 128, 256, 1,
                                     aAH, aAL, xinAH, xinAL, nullptr, nullptr,
                                     BAh, BAl, bl1 + 256, nullptr, xaH[0], xaL[0]);

    // ---- Layers 2..4 (Kseg = 256) ----
    int cur = 0;
    for (int l = 0; l < 3; l++) {
        k_aggp<256><<<aggBlkP, TPB>>>(xaH[cur], xaL[cur], rpW, colW, aWH, aWL, NP);
        k_aggp<256><<<aggBlkP, TPB>>>(xpH[cur], xpL[cur], rpC, colC, aCH, aCL, NP);
        k_aggp<256><<<aggBlkA, TPB>>>(xpH[cur], xpL[cur], rpA, colA, aAH, aAL, NA);
        const float* Wl_l = Wl + (size_t)l * 3 * 256 * 256;
        const float* Wr_l = Wr + (size_t)l * 3 * 256 * 256;
        const float* bl_l = bl + (size_t)l * 3 * 256;
        k_prepB<<<768, TPB>>>(Wl_l + 0 * 256 * 256, Wl_l + 2 * 256 * 256,
                              Wr_l + 0 * 256 * 256, Wr_l + 2 * 256 * 256,
                              256, 768, BPh, BPl);
        k_biascomb<<<1, 256>>>(bl_l + 0 * 256, bl_l + 2 * 256, bcomb);
        k_prepB<<<512, TPB>>>(Wl_l + 1 * 256 * 256, Wr_l + 1 * 256 * 256,
                              nullptr, nullptr, 256, 512, BAh, BAl);
        int relu = (l < 2) ? 1 : 0;
        k_mgemm<<<gP, TPB, SMEM_TOTAL>>>(NP, 768, 256, 256, relu,
                                         aWH, aWL, aCH, aCL, xpH[cur], xpL[cur],
                                         BPh, BPl, bcomb, nullptr,
                                         xpH[1 - cur], xpL[1 - cur]);
        k_mgemm<<<gA, TPB, SMEM_TOTAL>>>(NA, 512, 256, 256, relu,
                                         aAH, aAL, xaH[cur], xaL[cur], nullptr, nullptr,
                                         BAh, BAl, bl_l + 256, nullptr,
                                         xaH[1 - cur], xaL[1 - cur]);
        cur ^= 1;
    }

    // ---- Decoder ----
    k_prepDec<<<512, TPB>>>(dec_W1, BDh, BDl);
    k_mgemm<<<gD, TPB, SMEM_TOTAL>>>(NA, 256, 256, 512, 0,
                                     xaH[cur], xaL[cur], nullptr, nullptr,
                                     nullptr, nullptr,
                                     BDh, BDl, nullptr, TB, nullptr, nullptr);
    k_edge<<<(NEL * 32 + TPB - 1) / TPB, TPB>>>(esrc, edst, TB, dec_b1, dec_W2,
                                                dec_b2, out);
}

// round 5
// speedup vs baseline: 1.9965x; 1.1177x over previous
#include <cuda_runtime.h>
#include <cuda_bf16.h>
#include <cstdint>
#include <cstddef>

// ---------------------------------------------------------------------------
// Problem constants
// ---------------------------------------------------------------------------
#define NA   50000
#define NP   100000
#define NE   800000
#define NEL  100000
#define CD   256

typedef __nv_bfloat16 bf;

// ---------------------------------------------------------------------------
// Device scratch: activations as separate hi/lo bf16 planes
// ---------------------------------------------------------------------------
__device__ bf g_xaH[2][(size_t)NA * CD];
__device__ bf g_xaL[2][(size_t)NA * CD];
__device__ bf g_xpH[2][(size_t)NP * CD];
__device__ bf g_xpL[2][(size_t)NP * CD];
__device__ bf g_aWH[(size_t)NP * CD];
__device__ bf g_aWL[(size_t)NP * CD];
__device__ bf g_aCH[(size_t)NP * CD];
__device__ bf g_aCL[(size_t)NP * CD];
__device__ bf g_aAH[(size_t)NA * CD];
__device__ bf g_aAL[(size_t)NA * CD];
__device__ bf g_xinAH[(size_t)NA * 128];
__device__ bf g_xinAL[(size_t)NA * 128];
__device__ bf g_xinPH[(size_t)NP * 128];
__device__ bf g_xinPL[(size_t)NP * 128];
__device__ bf g_BPh[256 * 768];
__device__ bf g_BPl[256 * 768];
__device__ bf g_BAh[256 * 512];
__device__ bf g_BAl[256 * 512];
__device__ bf g_BDh[512 * 256];
__device__ bf g_BDl[512 * 256];
__device__ float g_bcomb[256];
__device__ float g_TB[(size_t)NA * 512];
// CSR
__device__ int g_rpW[NP + 1];
__device__ int g_rpC[NP + 1];
__device__ int g_rpA[NA + 1];
__device__ int g_colW[NE];
__device__ int g_colC[NE];
__device__ int g_colA[NE];
__device__ int g_cntW[NP];
__device__ int g_cntC[NP];
__device__ int g_cntA[NA];

// ---------------------------------------------------------------------------
// Baseline-PTX helpers (sm_80+: mma.sync bf16, ldmatrix, cp.async)
// ---------------------------------------------------------------------------
__device__ __forceinline__ uint32_t smem_u32(const void* p) {
    uint32_t a;
    asm("{ .reg .u64 t; cvta.to.shared.u64 t, %1; cvt.u32.u64 %0, t; }"
        : "=r"(a) : "l"(p));
    return a;
}
__device__ __forceinline__ void cpasync16(uint32_t dst, const void* src, int sz) {
    asm volatile("cp.async.cg.shared.global [%0], [%1], 16, %2;"
                 :: "r"(dst), "l"(src), "r"(sz) : "memory");
}
#define CP_COMMIT() asm volatile("cp.async.commit_group;" ::: "memory")
#define CP_WAIT1()  asm volatile("cp.async.wait_group 1;" ::: "memory")
#define CP_WAIT0()  asm volatile("cp.async.wait_group 0;" ::: "memory")

__device__ __forceinline__ void ldsm4(uint32_t* r, uint32_t addr) {
    asm volatile("ldmatrix.sync.aligned.m8n8.x4.shared.b16 {%0,%1,%2,%3}, [%4];"
                 : "=r"(r[0]), "=r"(r[1]), "=r"(r[2]), "=r"(r[3]) : "r"(addr));
}
__device__ __forceinline__ void mma16816(float* c, const uint32_t* a, const uint32_t* b) {
    asm volatile(
        "mma.sync.aligned.m16n8k16.row.col.f32.bf16.bf16.f32 "
        "{%0,%1,%2,%3}, {%4,%5,%6,%7}, {%8,%9}, {%0,%1,%2,%3};"
        : "+f"(c[0]), "+f"(c[1]), "+f"(c[2]), "+f"(c[3])
        : "r"(a[0]), "r"(a[1]), "r"(a[2]), "r"(a[3]), "r"(b[0]), "r"(b[1]));
}

// ---------------------------------------------------------------------------
// Split-precision helpers
// ---------------------------------------------------------------------------
__device__ __forceinline__ float2 cvt2(uint32_t w) {
    __nv_bfloat162 b = *reinterpret_cast<__nv_bfloat162*>(&w);
    return __bfloat1622float2(b);
}
__device__ __forceinline__ void split1(float v, bf& h, bf& l) {
    h = __float2bfloat16(v);
    l = __float2bfloat16(v - __bfloat162float(h));
}
__device__ __forceinline__ uint32_t packbf2(bf a, bf b) {
    __nv_bfloat162 p = __halves2bfloat162(a, b);
    return *reinterpret_cast<uint32_t*>(&p);
}

// ---------------------------------------------------------------------------
// CSR build: histogram -> merged scan (3 blocks) -> merged fill
// ---------------------------------------------------------------------------
__global__ void k_hist(const int* __restrict__ wdst, const int* __restrict__ cdst,
                       const int* __restrict__ wsrc) {
    for (int e = blockIdx.x * blockDim.x + threadIdx.x; e < NE; e += gridDim.x * blockDim.x) {
        atomicAdd(&g_cntW[wdst[e]], 1);
        atomicAdd(&g_cntC[cdst[e]], 1);
        atomicAdd(&g_cntA[wsrc[e]], 1);
    }
}

__device__ void scan_body(int* __restrict__ cnt, int* __restrict__ rp, int n) {
    __shared__ int wsum[32];
    __shared__ int carry;
    int t = threadIdx.x, lane = t & 31, wid = t >> 5;
    if (t == 0) carry = 0;
    __syncthreads();
    for (int base = 0; base < n; base += 1024) {
        int idx = base + t;
        int v = (idx < n) ? cnt[idx] : 0;
        int x = v;
        #pragma unroll
        for (int off = 1; off < 32; off <<= 1) {
            int y = __shfl_up_sync(0xffffffffu, x, off);
            if (lane >= off) x += y;
        }
        if (lane == 31) wsum[wid] = x;
        __syncthreads();
        if (wid == 0) {
            int s = wsum[lane];
            #pragma unroll
            for (int off = 1; off < 32; off <<= 1) {
                int y = __shfl_up_sync(0xffffffffu, s, off);
                if (lane >= off) s += y;
            }
            wsum[lane] = s;
        }
        __syncthreads();
        int offset = ((wid > 0) ? wsum[wid - 1] : 0) + carry;
        if (idx < n) rp[idx] = offset + x - v;
        __syncthreads();
        if (t == 0) carry += wsum[31];
        __syncthreads();
    }
    if (t == 0) rp[n] = carry;
    __syncthreads();
    // re-zero counters for use as fill cursors
    for (int i = t; i < n; i += blockDim.x) cnt[i] = 0;
}

__global__ void k_scan3() {
    if (blockIdx.x == 0)      scan_body(g_cntW, g_rpW, NP);
    else if (blockIdx.x == 1) scan_body(g_cntC, g_rpC, NP);
    else                      scan_body(g_cntA, g_rpA, NA);
}

__device__ void fill_body(const int* __restrict__ key, const int* __restrict__ val,
                          const int* __restrict__ rp, int* __restrict__ cur,
                          int* __restrict__ col, int rb, int nb) {
    for (int e = rb * blockDim.x + threadIdx.x; e < NE; e += nb * blockDim.x) {
        int k = key[e];
        int pos = rp[k] + atomicAdd(&cur[k], 1);
        col[pos] = val[e];
    }
}

#define FILLB 512
__global__ void k_fill3(const int* __restrict__ wdst, const int* __restrict__ wsrc,
                        const int* __restrict__ cdst, const int* __restrict__ csrc) {
    int job = blockIdx.x / FILLB, rb = blockIdx.x % FILLB;
    if (job == 0)      fill_body(wdst, wsrc, g_rpW, g_cntW, g_colW, rb, FILLB);
    else if (job == 1) fill_body(cdst, csrc, g_rpC, g_cntC, g_colC, rb, FILLB);
    else               fill_body(wsrc, wdst, g_rpA, g_cntA, g_colA, rb, FILLB);
}

// ---------------------------------------------------------------------------
// fp32 -> hi/lo planes (author + paper in one launch)
// ---------------------------------------------------------------------------
__global__ void k_split2(const float* __restrict__ xa, const float* __restrict__ xp) {
    const int n1 = NA * 128, n2 = NP * 128;
    for (int i = blockIdx.x * blockDim.x + threadIdx.x; i < n1 + n2;
         i += gridDim.x * blockDim.x) {
        bf h, l;
        if (i < n1) {
            split1(xa[i], h, l);
            g_xinAH[i] = h; g_xinAL[i] = l;
        } else {
            int j = i - n1;
            split1(xp[j], h, l);
            g_xinPH[j] = h; g_xinPL[j] = l;
        }
    }
}

// ---------------------------------------------------------------------------
// Merged mean aggregation: 3 jobs in one launch
// ---------------------------------------------------------------------------
struct AggJob {
    const bf *xh, *xl;
    const int *rp, *col;
    bf *oh, *ol;
    int ndst;
};

template <int DIM>
__device__ void agg_body(const AggJob& J, int rb, int nb) {
    constexpr int EPL = DIM / 32;
    constexpr int W = EPL / 2;
    int lane = threadIdx.x & 31;
    int w  = rb * (blockDim.x >> 5) + (threadIdx.x >> 5);
    int nw = nb * (blockDim.x >> 5);
    for (int d = w; d < J.ndst; d += nw) {
        int e0 = J.rp[d], e1 = J.rp[d + 1];
        float acc[EPL];
        #pragma unroll
        for (int j = 0; j < EPL; j++) acc[j] = 0.f;
        for (int e = e0; e < e1; e++) {
            size_t base = (size_t)J.col[e] * DIM + lane * EPL;
            uint32_t wh[W], wl[W];
            if (W == 4) {
                *(uint4*)wh = *(const uint4*)(J.xh + base);
                *(uint4*)wl = *(const uint4*)(J.xl + base);
            } else {
                *(uint2*)wh = *(const uint2*)(J.xh + base);
                *(uint2*)wl = *(const uint2*)(J.xl + base);
            }
            #pragma unroll
            for (int j = 0; j < W; j++) {
                float2 fh = cvt2(wh[j]), fl = cvt2(wl[j]);
                acc[2 * j]     += fh.x + fl.x;
                acc[2 * j + 1] += fh.y + fl.y;
            }
        }
        float inv = 1.0f / (float)max(e1 - e0, 1);
        uint32_t ohw[W], olw[W];
        #pragma unroll
        for (int j = 0; j < W; j++) {
            bf h0, l0, h1, l1;
            split1(acc[2 * j] * inv, h0, l0);
            split1(acc[2 * j + 1] * inv, h1, l1);
            ohw[j] = packbf2(h0, h1);
            olw[j] = packbf2(l0, l1);
        }
        size_t obase = (size_t)d * DIM + lane * EPL;
        if (W == 4) {
            *(uint4*)(J.oh + obase) = *(uint4*)ohw;
            *(uint4*)(J.ol + obase) = *(uint4*)olw;
        } else {
            *(uint2*)(J.oh + obase) = *(uint2*)ohw;
            *(uint2*)(J.ol + obase) = *(uint2*)olw;
        }
    }
}

template <int DIM>
__global__ void k_agg3(AggJob j0, AggJob j1, AggJob j2, int nb0, int nb1, int nb2) {
    int b = blockIdx.x;
    if (b < nb0)            agg_body<DIM>(j0, b, nb0);
    else if (b < nb0 + nb1) agg_body<DIM>(j1, b - nb0, nb1);
    else                    agg_body<DIM>(j2, b - nb0 - nb1, nb2);
}

// ---------------------------------------------------------------------------
// Weight prep (merged paper+author): B planes [256 x Ktot] from W segs [Kseg,256]
// ---------------------------------------------------------------------------
struct PrepJob {
    const float *W0, *W1s, *W2a, *W2b;
    int Kseg, Ktot;
    bf *Bh, *Bl;
};

__device__ void prep_body(const PrepJob& J, int rb, int nb) {
    int tot = 256 * J.Ktot;
    for (int i = rb * blockDim.x + threadIdx.x; i < tot; i += nb * blockDim.x) {
        int n = i / J.Ktot, kg = i - n * J.Ktot;
        int seg = kg / J.Kseg, k = kg - seg * J.Kseg;
        float v;
        if (seg == 0)      v = J.W0[k * 256 + n];
        else if (seg == 1) v = J.W1s[k * 256 + n];
        else               v = J.W2a[k * 256 + n] + J.W2b[k * 256 + n];
        bf h, l;
        split1(v, h, l);
        J.Bh[i] = h;
        J.Bl[i] = l;
    }
}

__global__ void k_prep2(PrepJob a, PrepJob b, int nba, int nbb) {
    int blk = blockIdx.x;
    if (blk < nba) prep_body(a, blk, nba);
    else           prep_body(b, blk - nba, nbb);
}

__global__ void k_prepDec(const float* __restrict__ W1) {
    for (int i = blockIdx.x * blockDim.x + threadIdx.x; i < 512 * 256;
         i += gridDim.x * blockDim.x) {
        int n = i >> 8, k = i & 255;
        float v = (n < 256) ? W1[k * 256 + n] : W1[(256 + k) * 256 + (n - 256)];
        bf h, l;
        split1(v, h, l);
        g_BDh[i] = h;
        g_BDl[i] = l;
    }
}

__global__ void k_biascomb(const float* __restrict__ a, const float* __restrict__ b,
                           float* __restrict__ o) {
    int i = threadIdx.x;
    if (i < 256) o[i] = a[i] + b[i];
}

// ---------------------------------------------------------------------------
// Split-bf16 tensor-core GEMM (mma.sync m16n8k16, cp.async double buffer)
// Two jobs merged in one launch (paper blocks: by < yP; author blocks after).
// ---------------------------------------------------------------------------
#define ROWB   80
#define OFF_AH 0
#define OFF_AL 10240
#define OFF_BH 20480
#define OFF_BL 30720
#define STAGE  40960
#define SMEM_TOTAL (2 * STAGE)

struct GemmP {
    int M, Ktot, Kseg, Nall, relu;
    const bf *A0h, *A0l, *A1h, *A1l, *A2h, *A2l, *Bh, *Bl;
    const float* bias;
    float* Cf;
    bf *Ch, *Cl;
};

__device__ __forceinline__ void stage_load(const GemmP& P, uint32_t sb, int stg,
                                           int tid, int bm, int n_off, int s) {
    int kg = s * 32;
    int seg = kg / P.Kseg;
    int kof = kg - seg * P.Kseg;
    const bf* ah = (seg == 0) ? P.A0h : (seg == 1) ? P.A1h : P.A2h;
    const bf* al = (seg == 0) ? P.A0l : (seg == 1) ? P.A1l : P.A2l;
    uint32_t base = sb + stg * STAGE;
    #pragma unroll
    for (int i = 0; i < 2; i++) {
        int c = tid + 256 * i;
        int row = c >> 2, kc = c & 3;
        uint32_t d = base + row * ROWB + kc * 16;
        int gr = bm + row;
        int sz = (gr < P.M) ? 16 : 0;
        int grc = (gr < P.M) ? gr : (P.M - 1);
        size_t aoff = (size_t)grc * P.Kseg + kof + kc * 8;
        cpasync16(d + OFF_AH, ah + aoff, sz);
        cpasync16(d + OFF_AL, al + aoff, sz);
        size_t boff = (size_t)(n_off + row) * P.Ktot + kg + kc * 8;
        cpasync16(d + OFF_BH, P.Bh + boff, 16);
        cpasync16(d + OFF_BL, P.Bl + boff, 16);
    }
}

__global__ void __launch_bounds__(256, 2)
k_mgemm2(GemmP p, GemmP q, int yP) {
    extern __shared__ char smem[];
    uint32_t sb = smem_u32(smem);
    int tid = threadIdx.x;
    int lane = tid & 31;
    int warp = tid >> 5;
    int wm = warp >> 2;
    int wn = warp & 3;

    GemmP P;
    int by = blockIdx.y;
    if (by < yP) P = p;
    else { P = q; by -= yP; }
    int bm = by * 128;
    int n_off = blockIdx.x * 128;
    int S = P.Ktot / 32;

    float acc[4][4][4];
    #pragma unroll
    for (int a = 0; a < 4; a++)
        #pragma unroll
        for (int b = 0; b < 4; b++)
            #pragma unroll
            for (int c = 0; c < 4; c++) acc[a][b][c] = 0.f;

    uint32_t lmo = (uint32_t)((lane & 15) * ROWB + (lane >> 4) * 16);

    stage_load(P, sb, 0, tid, bm, n_off, 0);
    CP_COMMIT();

    for (int s = 0; s < S; s++) {
        if (s + 1 < S) {
            stage_load(P, sb, (s + 1) & 1, tid, bm, n_off, s + 1);
            CP_COMMIT();
            CP_WAIT1();
        } else {
            CP_WAIT0();
        }
        __syncthreads();

        uint32_t base = sb + (s & 1) * STAGE;
        #pragma unroll
        for (int ks = 0; ks < 2; ks++) {
            uint32_t kb = ks * 32;
            uint32_t af[4][4], bhf[4][2], blf[4][2];
            #pragma unroll
            for (int mt = 0; mt < 4; mt++)
                ldsm4(af[mt], base + OFF_AH + (wm * 64 + mt * 16) * ROWB + kb + lmo);
            #pragma unroll
            for (int bt = 0; bt < 2; bt++) {
                uint32_t r[4];
                ldsm4(r, base + OFF_BH + (wn * 32 + bt * 16) * ROWB + kb + lmo);
                bhf[2 * bt][0] = r[0]; bhf[2 * bt][1] = r[2];
                bhf[2 * bt + 1][0] = r[1]; bhf[2 * bt + 1][1] = r[3];
            }
            #pragma unroll
            for (int bt = 0; bt < 2; bt++) {
                uint32_t r[4];
                ldsm4(r, base + OFF_BL + (wn * 32 + bt * 16) * ROWB + kb + lmo);
                blf[2 * bt][0] = r[0]; blf[2 * bt][1] = r[2];
                blf[2 * bt + 1][0] = r[1]; blf[2 * bt + 1][1] = r[3];
            }
            #pragma unroll
            for (int mt = 0; mt < 4; mt++)
                #pragma unroll
                for (int nt = 0; nt < 4; nt++) mma16816(acc[mt][nt], af[mt], bhf[nt]);
            #pragma unroll
            for (int mt = 0; mt < 4; mt++)
                #pragma unroll
                for (int nt = 0; nt < 4; nt++) mma16816(acc[mt][nt], af[mt], blf[nt]);
            #pragma unroll
            for (int mt = 0; mt < 4; mt++)
                ldsm4(af[mt], base + OFF_AL + (wm * 64 + mt * 16) * ROWB + kb + lmo);
            #pragma unroll
            for (int mt = 0; mt < 4; mt++)
                #pragma unroll
                for (int nt = 0; nt < 4; nt++) mma16816(acc[mt][nt], af[mt], bhf[nt]);
        }
        __syncthreads();
    }

    // Epilogue
    #pragma unroll
    for (int mt = 0; mt < 4; mt++) {
        int r0 = bm + wm * 64 + mt * 16 + (lane >> 2);
        #pragma unroll
        for (int half = 0; half < 2; half++) {
            int row = r0 + half * 8;
            if (row >= P.M) continue;
            #pragma unroll
            for (int nt = 0; nt < 4; nt++) {
                int gcol = n_off + wn * 32 + nt * 8 + (lane & 3) * 2;
                float v0 = acc[mt][nt][half * 2 + 0];
                float v1 = acc[mt][nt][half * 2 + 1];
                if (P.Cf) {
                    *(float2*)(P.Cf + (size_t)row * P.Nall + gcol) = make_float2(v0, v1);
                } else {
                    v0 += P.bias[gcol];
                    v1 += P.bias[gcol + 1];
                    if (P.relu) { v0 = fmaxf(v0, 0.f); v1 = fmaxf(v1, 0.f); }
                    bf h0, l0, h1, l1;
                    split1(v0, h0, l0);
                    split1(v1, h1, l1);
                    *(uint32_t*)(P.Ch + (size_t)row * P.Nall + gcol) = packbf2(h0, h1);
                    *(uint32_t*)(P.Cl + (size_t)row * P.Nall + gcol) = packbf2(l0, l1);
                }
            }
        }
    }
}

// ---------------------------------------------------------------------------
// Fused edge decoder
// ---------------------------------------------------------------------------
__global__ void k_edge(const int* __restrict__ src, const int* __restrict__ dst,
                       const float* __restrict__ TB, const float* __restrict__ b1,
                       const float* __restrict__ W2, const float* __restrict__ b2,
                       float* __restrict__ out) {
    int lane = threadIdx.x & 31;
    int w  = (blockIdx.x * blockDim.x + threadIdx.x) >> 5;
    int nw = (gridDim.x * blockDim.x) >> 5;
    for (int e = w; e < NEL; e += nw) {
        int s = src[e], d = dst[e];
        const float* Ts = TB + (size_t)s * 512;
        const float* Td = TB + (size_t)d * 512 + 256;
        float sum = 0.f;
        #pragma unroll
        for (int k = 0; k < 8; k++) {
            int c = lane + 32 * k;
            float h = Ts[c] + Td[c] + b1[c];
            h = fmaxf(h, 0.f);
            sum += h * W2[c];
        }
        #pragma unroll
        for (int off = 16; off; off >>= 1)
            sum += __shfl_down_sync(0xffffffffu, sum, off);
        if (lane == 0) out[e] = sum + b2[0];
    }
}

// ---------------------------------------------------------------------------
// Host
// ---------------------------------------------------------------------------
template <typename T>
static T* sym_addr(const void* sym) {
    void* p = nullptr;
    cudaGetSymbolAddress(&p, sym);
    return (T*)p;
}

extern "C" void kernel_launch(void* const* d_in, const int* in_sizes, int n_in,
                              void* d_out, int out_size) {
    const float* x_author = (const float*)d_in[0];
    const float* x_paper  = (const float*)d_in[1];
    const float* Wl1      = (const float*)d_in[2];
    const float* bl1      = (const float*)d_in[3];
    const float* Wr1      = (const float*)d_in[4];
    const float* Wl       = (const float*)d_in[5];
    const float* bl       = (const float*)d_in[6];
    const float* Wr       = (const float*)d_in[7];
    const float* dec_W1   = (const float*)d_in[8];
    const float* dec_b1   = (const float*)d_in[9];
    const float* dec_W2   = (const float*)d_in[10];
    const float* dec_b2   = (const float*)d_in[11];
    const int* wsrc = (const int*)d_in[12];
    const int* wdst = (const int*)d_in[13];
    const int* csrc = (const int*)d_in[14];
    const int* cdst = (const int*)d_in[15];
    const int* esrc = (const int*)d_in[16];
    const int* edst = (const int*)d_in[17];
    float* out = (float*)d_out;

    bf* xaH[2] = {sym_addr<bf>(g_xaH), sym_addr<bf>(g_xaH) + (size_t)NA * CD};
    bf* xaL[2] = {sym_addr<bf>(g_xaL), sym_addr<bf>(g_xaL) + (size_t)NA * CD};
    bf* xpH[2] = {sym_addr<bf>(g_xpH), sym_addr<bf>(g_xpH) + (size_t)NP * CD};
    bf* xpL[2] = {sym_addr<bf>(g_xpL), sym_addr<bf>(g_xpL) + (size_t)NP * CD};
    bf* aWH = sym_addr<bf>(g_aWH); bf* aWL = sym_addr<bf>(g_aWL);
    bf* aCH = sym_addr<bf>(g_aCH); bf* aCL = sym_addr<bf>(g_aCL);
    bf* aAH = sym_addr<bf>(g_aAH); bf* aAL = sym_addr<bf>(g_aAL);
    bf* xinAH = sym_addr<bf>(g_xinAH); bf* xinAL = sym_addr<bf>(g_xinAL);
    bf* xinPH = sym_addr<bf>(g_xinPH); bf* xinPL = sym_addr<bf>(g_xinPL);
    bf* BPh = sym_addr<bf>(g_BPh); bf* BPl = sym_addr<bf>(g_BPl);
    bf* BAh = sym_addr<bf>(g_BAh); bf* BAl = sym_addr<bf>(g_BAl);
    bf* BDh = sym_addr<bf>(g_BDh); bf* BDl = sym_addr<bf>(g_BDl);
    float* bcomb = sym_addr<float>(g_bcomb);
    float* TB = sym_addr<float>(g_TB);
    int* rpW = sym_addr<int>(g_rpW);
    int* rpC = sym_addr<int>(g_rpC);
    int* rpA = sym_addr<int>(g_rpA);
    int* colW = sym_addr<int>(g_colW);
    int* colC = sym_addr<int>(g_colC);
    int* colA = sym_addr<int>(g_colA);
    int* cntW = sym_addr<int>(g_cntW);
    int* cntC = sym_addr<int>(g_cntC);
    int* cntA = sym_addr<int>(g_cntA);

    cudaFuncSetAttribute(k_mgemm2, cudaFuncAttributeMaxDynamicSharedMemorySize, SMEM_TOTAL);

    const int TPB = 256;
    const int nbP = (NP + 7) / 8;    // 12500 agg blocks (8 warps/block)
    const int nbA = (NA + 7) / 8;    // 6250

    // ---- CSR build ----
    cudaMemsetAsync(cntW, 0, NP * sizeof(int));
    cudaMemsetAsync(cntC, 0, NP * sizeof(int));
    cudaMemsetAsync(cntA, 0, NA * sizeof(int));
    k_hist<<<1024, TPB>>>(wdst, cdst, wsrc);
    k_scan3<<<3, 1024>>>();
    k_fill3<<<3 * FILLB, TPB>>>(wdst, wsrc, cdst, csrc);

    // ---- Split fp32 inputs ----
    k_split2<<<2048, TPB>>>(x_author, x_paper);

    AggJob jW, jC, jA;
    jW.rp = rpW; jW.col = colW; jW.oh = aWH; jW.ol = aWL; jW.ndst = NP;
    jC.rp = rpC; jC.col = colC; jC.oh = aCH; jC.ol = aCL; jC.ndst = NP;
    jA.rp = rpA; jA.col = colA; jA.oh = aAH; jA.ol = aAL; jA.ndst = NA;

    GemmP gp, ga;
    gp.Nall = 256; ga.Nall = 256;
    gp.Cf = nullptr; ga.Cf = nullptr;
    gp.A0h = aWH; gp.A0l = aWL; gp.A1h = aCH; gp.A1l = aCL;
    gp.Bh = BPh; gp.Bl = BPl; gp.bias = bcomb; gp.M = NP;
    ga.A0h = aAH; ga.A0l = aAL; ga.A2h = nullptr; ga.A2l = nullptr;
    ga.Bh = BAh; ga.Bl = BAl; ga.M = NA;

    PrepJob pjP, pjA;
    pjP.Bh = BPh; pjP.Bl = BPl;
    pjA.Bh = BAh; pjA.Bl = BAl;
    pjA.W2a = nullptr; pjA.W2b = nullptr;

    const int yP = (NP + 127) / 128;   // 782
    const int yA = (NA + 127) / 128;   // 391
    dim3 gridPA(2, yP + yA);
    dim3 gridD(4, yA);

    // ---- Layer 1 (Kseg = 128) ----
    jW.xh = xinAH; jW.xl = xinAL;
    jC.xh = xinPH; jC.xl = xinPL;
    jA.xh = xinPH; jA.xl = xinPL;
    k_agg3<128><<<2 * nbP + nbA, TPB>>>(jW, jC, jA, nbP, nbP, nbA);
    pjP.W0 = Wl1 + 0 * 128 * 256; pjP.W1s = Wl1 + 2 * 128 * 256;
    pjP.W2a = Wr1 + 0 * 128 * 256; pjP.W2b = Wr1 + 2 * 128 * 256;
    pjP.Kseg = 128; pjP.Ktot = 384;
    pjA.W0 = Wl1 + 1 * 128 * 256; pjA.W1s = Wr1 + 1 * 128 * 256;
    pjA.Kseg = 128; pjA.Ktot = 256;
    k_prep2<<<384, TPB>>>(pjP, pjA, 256, 128);
    k_biascomb<<<1, 256>>>(bl1 + 0 * 256, bl1 + 2 * 256, bcomb);
    gp.Ktot = 384; gp.Kseg = 128; gp.relu = 1;
    gp.A2h = xinPH; gp.A2l = xinPL;
    gp.Ch = xpH[0]; gp.Cl = xpL[0];
    ga.Ktot = 256; ga.Kseg = 128; ga.relu = 1;
    ga.A1h = xinAH; ga.A1l = xinAL;
    ga.bias = bl1 + 256;
    ga.Ch = xaH[0]; ga.Cl = xaL[0];
    k_mgemm2<<<gridPA, TPB, SMEM_TOTAL>>>(gp, ga, yP);

    // ---- Layers 2..4 (Kseg = 256) ----
    int cur = 0;
    for (int l = 0; l < 3; l++) {
        jW.xh = xaH[cur]; jW.xl = xaL[cur];
        jC.xh = xpH[cur]; jC.xl = xpL[cur];
        jA.xh = xpH[cur]; jA.xl = xpL[cur];
        k_agg3<256><<<2 * nbP + nbA, TPB>>>(jW, jC, jA, nbP, nbP, nbA);
        const float* Wl_l = Wl + (size_t)l * 3 * 256 * 256;
        const float* Wr_l = Wr + (size_t)l * 3 * 256 * 256;
        const float* bl_l = bl + (size_t)l * 3 * 256;
        pjP.W0 = Wl_l + 0 * 256 * 256; pjP.W1s = Wl_l + 2 * 256 * 256;
        pjP.W2a = Wr_l + 0 * 256 * 256; pjP.W2b = Wr_l + 2 * 256 * 256;
        pjP.Kseg = 256; pjP.Ktot = 768;
        pjA.W0 = Wl_l + 1 * 256 * 256; pjA.W1s = Wr_l + 1 * 256 * 256;
        pjA.Kseg = 256; pjA.Ktot = 512;
        k_prep2<<<768, TPB>>>(pjP, pjA, 512, 256);
        k_biascomb<<<1, 256>>>(bl_l + 0 * 256, bl_l + 2 * 256, bcomb);
        int relu = (l < 2) ? 1 : 0;
        gp.Ktot = 768; gp.Kseg = 256; gp.relu = relu;
        gp.A2h = xpH[cur]; gp.A2l = xpL[cur];
        gp.Ch = xpH[1 - cur]; gp.Cl = xpL[1 - cur];
        ga.Ktot = 512; ga.Kseg = 256; ga.relu = relu;
        ga.A1h = xaH[cur]; ga.A1l = xaL[cur];
        ga.bias = bl_l + 256;
        ga.Ch = xaH[1 - cur]; ga.Cl = xaL[1 - cur];
        k_mgemm2<<<gridPA, TPB, SMEM_TOTAL>>>(gp, ga, yP);
        cur ^= 1;
    }

    // ---- Decoder ----
    k_prepDec<<<512, TPB>>>(dec_W1);
    GemmP gd;
    gd.M = NA; gd.Ktot = 256; gd.Kseg = 256; gd.Nall = 512; gd.relu = 0;
    gd.A0h = xaH[cur]; gd.A0l = xaL[cur];
    gd.A1h = nullptr; gd.A1l = nullptr; gd.A2h = nullptr; gd.A2l = nullptr;
    gd.Bh = BDh; gd.Bl = BDl; gd.bias = nullptr;
    gd.Cf = TB; gd.Ch = nullptr; gd.Cl = nullptr;
    k_mgemm2<<<gridD, TPB, SMEM_TOTAL>>>(gd, gd, yA + 1);
    k_edge<<<(NEL * 32 + TPB - 1) / TPB, TPB>>>(esrc, edst, TB, dec_b1, dec_W2,
                                                dec_b2, out);
}